// round 9
// baseline (speedup 1.0000x reference)
#include <cuda_runtime.h>

// ---------------------------------------------------------------------------
// Quantized LeNet, exact fixed-point semantics.
// APREC=8, PPREC=8, IWIDTH=3 -> clamp to [-8.0, +7.0], grid 1/256.
//
// round_half_even(x*w256) == fmaf(x, w256, MAGIC) - MAGIC (MAGIC=1.5*2^23).
// Conv fast path (per-block proof the clamp is a no-op): fma.rn.f32x2 rounds
// TWO pixels per fma; IADD3 merges two 32-bit halves per alu op; magic bias
// removed once via acc init = bias - ntaps*MAGICI (mod 2^32).
// R9: distance-pairing — outputs packed (out[j], out[j+D]) so every f32x2
// operand is an ALIGNED smem pack D[m]=(x[m],x[m+D]); kills all mkpack MOVs
// in the hot loops. fc phase1 vectorized, FC1 4 accumulator chains.
// Clamped scalar fallback per block keeps ANY input exact.
// ---------------------------------------------------------------------------

typedef unsigned long long ull;

#define MAGICF 12582912.0f
#define MAGICI 0x4B400000u
#define MAGICIi 0x4B400000
#define MAGIC2 0x4B4000004B400000ULL
#define CLAMP_LO (MAGICF - 2048.0f)
#define CLAMP_HI (MAGICF + 1792.0f)   // QMAX = +7.0
#define QLO (-2048)
#define QHI 1792
#define SAFE_BOUND 458624             // 1792*256 - 128

#define OFF_LOGP   0
#define OFF_C1IN   20480
#define OFF_C1OUT  1626112
#define OFF_C2IN   13422592
#define OFF_C2OUT  16371712
#define OFF_FC1IN  18993152
#define OFF_FC1OUT 19648512
#define OFF_FC2IN  19750912
#define OFF_FC2OUT 19853312

__device__ ull   g_w1b[256];         // conv1 w*256 broadcast pairs (w,w)
__device__ int   g_b1[16];
__device__ ull   g_w2b[6016];        // conv2 broadcast pairs, [20][10][5][6]
__device__ int   g_b2[32];
__device__ short g_w1t[320 * 64];    // fc1 w transposed [k][o], o padded to 64
__device__ int   g_f1b[64];
__device__ short g_w2t[50 * 16];     // fc2 w transposed [k][o], o padded to 16
__device__ int   g_f2b[16];
__device__ int   g_maxw1 = 0;        // idempotent atomicMax targets
__device__ int   g_maxw2 = 0;

__device__ __forceinline__ int iclamp(int v, int lo, int hi) {
    return v < lo ? lo : (v > hi ? hi : v);
}
__device__ __forceinline__ int rhe8(int S) {
    return (S + 127 + ((S >> 8) & 1)) >> 8;
}
__device__ __forceinline__ unsigned lo32(ull v) { return (unsigned)v; }
__device__ __forceinline__ unsigned hi32(ull v) { return (unsigned)(v >> 32); }
__device__ __forceinline__ ull mkpackf(float lo, float hi) {
    ull d;
    asm("mov.b64 %0, {%1, %2};" : "=l"(d) : "f"(lo), "f"(hi));
    return d;
}
__device__ __forceinline__ ull ffma2m(ull x, ull w) {
    ull d;
    ull m = MAGIC2;
    asm("fma.rn.f32x2 %0, %1, %2, %3;" : "=l"(d) : "l"(x), "l"(w), "l"(m));
    return d;
}

template <int NW>
__device__ __forceinline__ void blockAtomicMax(int v, int* dst) {
    __shared__ int sm[NW];
    v = __reduce_max_sync(0xffffffffu, v);
    int w = threadIdx.x >> 5;
    if ((threadIdx.x & 31) == 0) sm[w] = v;
    __syncthreads();
    if (threadIdx.x == 0) {
        int m = sm[0];
#pragma unroll
        for (int i = 1; i < NW; i++) m = max(m, sm[i]);
        atomicMax(dst, m);
    }
}

// ---------------------------------------------------------------------------
// prep: 64 blocks x 256 threads, grid-stride over every table.
__global__ void __launch_bounds__(256) prep_kernel(
        const float* __restrict__ w1, const float* __restrict__ b1,
        const float* __restrict__ w2, const float* __restrict__ b2,
        const float* __restrict__ f1w, const float* __restrict__ f1b,
        const float* __restrict__ f2w, const float* __restrict__ f2b) {
    int gt = blockIdx.x * 256 + threadIdx.x;
    const int gs = 64 * 256;
    int m1 = 0, m2 = 0;

    for (int i = gt; i < 250; i += gs) {
        float q = rintf(w1[i] * 256.0f);
        unsigned u = __float_as_uint(q);
        g_w1b[i] = ((ull)u << 32) | u;
        m1 = max(m1, abs((int)q));
    }
    for (int i = gt; i < 10; i += gs) g_b1[i] = __float2int_rn(b1[i] * 256.0f);
    for (int i = gt; i < 6000; i += gs) {
        int q = i % 6;
        int rest = i / 6;
        int p = rest % 5;
        int cc = rest / 5;            // cout*10 + cin
        int cin = cc % 10;
        int cout = cc / 10;
        float v = 0.0f;
        if (q < 5) {
            v = rintf(w2[((cout * 10 + cin) * 5 + p) * 5 + q] * 256.0f);
            m2 = max(m2, abs((int)v));
        }
        unsigned u = __float_as_uint(v);
        g_w2b[i] = ((ull)u << 32) | u;
    }
    for (int i = gt; i < 20; i += gs) g_b2[i] = __float2int_rn(b2[i] * 256.0f);

    for (int i = gt; i < 320 * 64; i += gs) {
        int k = i >> 6;
        int o = i & 63;
        short v = 0;
        if (o < 50) v = (short)iclamp(__float2int_rn(f1w[o * 320 + k] * 256.0f),
                                      QLO, QHI);
        g_w1t[i] = v;
    }
    for (int i = gt; i < 50; i += gs)
        g_f1b[i] = iclamp(__float2int_rn(f1b[i] * 256.0f), QLO, QHI);
    for (int i = gt; i < 50 * 16; i += gs) {
        int k = i >> 4;
        int o = i & 15;
        short v = 0;
        if (o < 10) v = (short)iclamp(__float2int_rn(f2w[o * 50 + k] * 256.0f),
                                      QLO, QHI);
        g_w2t[i] = v;
    }
    for (int i = gt; i < 10; i += gs)
        g_f2b[i] = iclamp(__float2int_rn(f2b[i] * 256.0f), QLO, QHI);

    blockAtomicMax<8>(m1, &g_maxw1);
    __syncthreads();
    blockAtomicMax<8>(m2, &g_maxw2);
}

// ---------------------------------------------------------------------------
// conv1 (+ input quant + pool1), one image per 256-thread block.
// Thread = (co, R, h): conv1_out rows 2R,2R+1 cols [12h,12h+12), pooled
// row R cols [6h,6h+6). Pairing: (out[c], out[c+6]) -> D[m]=(x[m],x[m+6]).

__device__ __forceinline__ void c1taps6(unsigned* aLo, unsigned* aHi,
                                        const ull* D, const ull* w) {
    ull w0 = w[0];
    ull w1 = w[1];
    ull w2 = w[2];
    ull w3 = w[3];
    ull w4 = w[4];
#pragma unroll
    for (int j = 0; j < 6; j++) {
        ull y0 = ffma2m(D[j], w0);
        ull y1 = ffma2m(D[j + 1], w1);
        ull y2 = ffma2m(D[j + 2], w2);
        ull y3 = ffma2m(D[j + 3], w3);
        ull y4 = ffma2m(D[j + 4], w4);
        aLo[j] = aLo[j] + lo32(y0) + lo32(y1);
        aLo[j] = aLo[j] + lo32(y2) + lo32(y3);
        aLo[j] = aLo[j] + lo32(y4);
        aHi[j] = aHi[j] + hi32(y0) + hi32(y1);
        aHi[j] = aHi[j] + hi32(y2) + hi32(y3);
        aHi[j] = aHi[j] + hi32(y4);
    }
}

__device__ __forceinline__ float i2f8(int v) {
    return __int2float_rn(v) * 0.00390625f;
}

// acc layout: Lo[j] = out[12h+j], Hi[j] = out[12h+6+j], j=0..5 (per row)
__device__ __forceinline__ void conv1_epilogue(float* dout, int b, int co, int R,
                                               int h,
                                               const int* a0L, const int* a0H,
                                               const int* a1L, const int* a1H) {
    float* Ox = dout + OFF_C1OUT + ((b * 10 + co) * 24 + 2 * R) * 24 + 12 * h;
    float4 v;
    v.x = i2f8(a0L[0]); v.y = i2f8(a0L[1]); v.z = i2f8(a0L[2]); v.w = i2f8(a0L[3]);
    *(float4*)(Ox + 0) = v;
    v.x = i2f8(a0L[4]); v.y = i2f8(a0L[5]); v.z = i2f8(a0H[0]); v.w = i2f8(a0H[1]);
    *(float4*)(Ox + 4) = v;
    v.x = i2f8(a0H[2]); v.y = i2f8(a0H[3]); v.z = i2f8(a0H[4]); v.w = i2f8(a0H[5]);
    *(float4*)(Ox + 8) = v;
    v.x = i2f8(a1L[0]); v.y = i2f8(a1L[1]); v.z = i2f8(a1L[2]); v.w = i2f8(a1L[3]);
    *(float4*)(Ox + 24) = v;
    v.x = i2f8(a1L[4]); v.y = i2f8(a1L[5]); v.z = i2f8(a1H[0]); v.w = i2f8(a1H[1]);
    *(float4*)(Ox + 28) = v;
    v.x = i2f8(a1H[2]); v.y = i2f8(a1H[3]); v.z = i2f8(a1H[4]); v.w = i2f8(a1H[5]);
    *(float4*)(Ox + 32) = v;

    // pooled row R cols 6h..6h+5:
    // pairs: (L0,L1),(L2,L3),(L4,L5),(H0,H1),(H2,H3),(H4,H5) across both rows
    int pc[6];
    pc[0] = max(max(a0L[0], a0L[1]), max(a1L[0], a1L[1]));
    pc[1] = max(max(a0L[2], a0L[3]), max(a1L[2], a1L[3]));
    pc[2] = max(max(a0L[4], a0L[5]), max(a1L[4], a1L[5]));
    pc[3] = max(max(a0H[0], a0H[1]), max(a1H[0], a1H[1]));
    pc[4] = max(max(a0H[2], a0H[3]), max(a1H[2], a1H[3]));
    pc[5] = max(max(a0H[4], a0H[5]), max(a1H[4], a1H[5]));
    float* P = dout + OFF_C2IN + ((b * 10 + co) * 12 + R) * 12 + 6 * h;
#pragma unroll
    for (int j = 0; j < 6; j += 2) {
        float2 v2;
        v2.x = max(pc[j + 0], 0) * 0.00390625f;
        v2.y = max(pc[j + 1], 0) * 0.00390625f;
        *(float2*)(P + j) = v2;
    }
}

__global__ void __launch_bounds__(256) conv1_kernel(const float4* __restrict__ xin,
                                                    float* __restrict__ dout) {
    __shared__ __align__(16) float sx[784];
    __shared__ __align__(16) ull sd[672];   // 28 rows x 24, D[m]=(x[m],x[m+6])
    __shared__ __align__(16) ull sw[256];
    __shared__ int red[8];

    int b = blockIdx.x;
    int t = threadIdx.x;

    int mx = 0;
    if (t < 196) {
        float4 v = xin[b * 196 + t];
        int q0 = __float2int_rn(v.x * 256.0f);
        int q1 = __float2int_rn(v.y * 256.0f);
        int q2 = __float2int_rn(v.z * 256.0f);
        int q3 = __float2int_rn(v.w * 256.0f);
        v.x = q0 * 0.00390625f; v.y = q1 * 0.00390625f;
        v.z = q2 * 0.00390625f; v.w = q3 * 0.00390625f;
        ((float4*)sx)[t] = v;
        ((float4*)(dout + OFF_C1IN + b * 784))[t] = v;
        mx = max(max(abs(q0), abs(q1)), max(abs(q2), abs(q3)));
    }
    if (t < 250) sw[t] = g_w1b[t];
    mx = __reduce_max_sync(0xffffffffu, mx);
    if ((t & 31) == 0) red[t >> 5] = mx;
    __syncthreads();

    // build D packs: sd[r*24+m] = (x[r][m], x[r][m+6]), m=0..21
#pragma unroll
    for (int ii = 0; ii < 3; ii++) {
        int i = ii * 256 + t;
        if (i < 672) {
            int r = i / 24;
            int m = i % 24;
            float lo = sx[r * 28 + m];                       // m<=23 < 28
            float hi = (m < 22) ? sx[r * 28 + m + 6] : 0.0f; // m+6<=27
            sd[i] = mkpackf(lo, hi);
        }
    }
    int xmax = red[0];
#pragma unroll
    for (int i = 1; i < 8; i++) xmax = max(xmax, red[i]);
    bool safe = (long long)xmax * (long long)g_maxw1 <= SAFE_BOUND;
    __syncthreads();

    if (t >= 240) return;
    int co = t / 24;
    int rem = t % 24;
    int R = rem >> 1;
    int h = t & 1;

    if (safe) {
        unsigned bias = (unsigned)g_b1[co] - 25u * MAGICI;
        unsigned a0L[6], a0H[6], a1L[6], a1H[6];
#pragma unroll
        for (int j = 0; j < 6; j++) { a0L[j] = bias; a0H[j] = bias;
                                      a1L[j] = bias; a1H[j] = bias; }
#pragma unroll
        for (int rr = 0; rr < 6; rr++) {
            ull D[10];
            const ull* dp = sd + (2 * R + rr) * 24 + 12 * h;
#pragma unroll
            for (int i = 0; i < 10; i += 2) {
                ulonglong2 v = *(const ulonglong2*)(dp + i);
                D[i] = v.x;
                D[i + 1] = v.y;
            }
            if (rr < 5)  c1taps6(a0L, a0H, D, sw + co * 25 + rr * 5);
            if (rr >= 1) c1taps6(a1L, a1H, D, sw + co * 25 + (rr - 1) * 5);
        }
        conv1_epilogue(dout, b, co, R, h, (const int*)a0L, (const int*)a0H,
                       (const int*)a1L, (const int*)a1H);
    } else {
        int bq = g_b1[co];
        int a0[12], a1[12];
#pragma unroll
        for (int j = 0; j < 12; j++) { a0[j] = bq; a1[j] = bq; }
        const float* X = sx + R * 56 + 12 * h;
#pragma unroll
        for (int rr = 0; rr < 6; rr++) {
            float xr[16];
#pragma unroll
            for (int i = 0; i < 4; i++) {
                float4 v = ((const float4*)(X + rr * 28))[i];
                xr[4 * i + 0] = v.x; xr[4 * i + 1] = v.y;
                xr[4 * i + 2] = v.z; xr[4 * i + 3] = v.w;
            }
#pragma unroll
            for (int pass = 0; pass < 2; pass++) {
                int p = pass == 0 ? rr : rr - 1;
                if (p < 0 || p > 4) continue;
                int* acc = pass == 0 ? a0 : a1;
#pragma unroll
                for (int q = 0; q < 5; q++) {
                    float w = __uint_as_float(lo32(sw[co * 25 + p * 5 + q]));
#pragma unroll
                    for (int j = 0; j < 12; j++) {
                        float y = fmaf(xr[j + q], w, MAGICF);
                        y = fminf(fmaxf(y, CLAMP_LO), CLAMP_HI);
                        acc[j] += __float_as_int(y) - MAGICIi;
                    }
                }
            }
        }
        // remap to Lo/Hi layout for the shared epilogue
        int a0L[6], a0H[6], a1L[6], a1H[6];
#pragma unroll
        for (int j = 0; j < 6; j++) {
            a0L[j] = a0[j]; a0H[j] = a0[j + 6];
            a1L[j] = a1[j]; a1H[j] = a1[j + 6];
        }
        conv1_epilogue(dout, b, co, R, h, a0L, a0H, a1L, a1H);
    }
}

// ---------------------------------------------------------------------------
// conv2: block = 160 threads = (2 images x 10 couts x 8 rows).
// Pairing: (out[j], out[j+4]) -> D[m]=(x[m],x[m+4]), m=0..7 per 12-float row.

template <bool CONSUME>
__device__ __forceinline__ void c2step(unsigned aL[4], unsigned aH[4],
                                       ull carry[4], const ull* dp,
                                       const ull* wp) {
    ull D[8];
#pragma unroll
    for (int i = 0; i < 8; i += 2) {
        ulonglong2 v = *(const ulonglong2*)(dp + i);
        D[i] = v.x;
        D[i + 1] = v.y;
    }
    const ulonglong2* wv = (const ulonglong2*)wp;
    ulonglong2 wa = wv[0];
    ulonglong2 wb = wv[1];
    ulonglong2 wc = wv[2];
#pragma unroll
    for (int j = 0; j < 4; j++) {
        ull y0 = ffma2m(D[j], wa.x);
        ull y1 = ffma2m(D[j + 1], wa.y);
        ull y2 = ffma2m(D[j + 2], wb.x);
        ull y3 = ffma2m(D[j + 3], wb.y);
        ull y4 = ffma2m(D[j + 4], wc.x);
        aL[j] = aL[j] + lo32(y0) + lo32(y1);
        aL[j] = aL[j] + lo32(y2) + lo32(y3);
        aH[j] = aH[j] + hi32(y0) + hi32(y1);
        aH[j] = aH[j] + hi32(y2) + hi32(y3);
        if (CONSUME) {
            aL[j] = aL[j] + lo32(y4) + lo32(carry[j]);
            aH[j] = aH[j] + hi32(y4) + hi32(carry[j]);
        } else {
            carry[j] = y4;
        }
    }
}

__global__ void __launch_bounds__(160) conv2_kernel(float* __restrict__ dout) {
    __shared__ __align__(16) float sx[2880];
    __shared__ __align__(16) ull sd[1920];   // 240 rows x 8, D[m]=(x[m],x[m+4])
    __shared__ __align__(16) ull sw[3000];
    __shared__ int red[5];

    int blk = blockIdx.x;     // 0..2047
    int ip = blk >> 1;        // image pair index
    int g = blk & 1;          // cout group (couts 10g..10g+9)
    int t = threadIdx.x;

    const ulonglong2* wsrc = (const ulonglong2*)(g_w2b + g * 3000);
    for (int i = t; i < 1500; i += 160) ((ulonglong2*)sw)[i] = wsrc[i];

    const float4* xs = (const float4*)(dout + OFF_C2IN + ip * 2880);
    int mx = 0;
    for (int i = t; i < 720; i += 160) {
        float4 v = xs[i];
        ((float4*)sx)[i] = v;
        int q0 = __float2int_rn(v.x * 256.0f);
        int q1 = __float2int_rn(v.y * 256.0f);
        int q2 = __float2int_rn(v.z * 256.0f);
        int q3 = __float2int_rn(v.w * 256.0f);
        mx = max(mx, max(max(abs(q0), abs(q1)), max(abs(q2), abs(q3))));
    }
    mx = __reduce_max_sync(0xffffffffu, mx);
    if ((t & 31) == 0) red[t >> 5] = mx;
    __syncthreads();

    // build D packs: sd[row*8+m] = (x[row][m], x[row][m+4]), m=0..7
    for (int i = t; i < 1920; i += 160) {
        int row = i >> 3;
        int m = i & 7;
        sd[i] = mkpackf(sx[row * 12 + m], sx[row * 12 + m + 4]);
    }
    int xmax = red[0];
#pragma unroll
    for (int i = 1; i < 5; i++) xmax = max(xmax, red[i]);
    bool safe = (long long)xmax * (long long)g_maxw2 <= SAFE_BOUND;
    __syncthreads();

    int img = t / 80;
    int r = t % 80;
    int co_local = r / 8;
    int row = r % 8;
    int co = g * 10 + co_local;
    const ull* W = sw + co_local * 300;
    int bi = ip * 2 + img;

    if (safe) {
        unsigned aL[4], aH[4];
        unsigned bias = (unsigned)g_b2[co] - 250u * MAGICI;
#pragma unroll
        for (int j = 0; j < 4; j++) { aL[j] = bias; aH[j] = bias; }
        ull carry[4];
        const ull* Dbase = sd + img * 960 + row * 8;   // row r of channel ci at +ci*96
#pragma unroll 1
        for (int ci2 = 0; ci2 < 5; ci2++) {
            int cA = 2 * ci2;
            const ull* Da = Dbase + cA * 96;
            const ull* Wa = W + cA * 30;
            c2step<false>(aL, aH, carry, Da + 0 * 8, Wa + 0);
            c2step<true >(aL, aH, carry, Da + 1 * 8, Wa + 6);
            c2step<false>(aL, aH, carry, Da + 2 * 8, Wa + 12);
            c2step<true >(aL, aH, carry, Da + 3 * 8, Wa + 18);
            c2step<false>(aL, aH, carry, Da + 4 * 8, Wa + 24);
            const ull* Db = Da + 96;
            const ull* Wb = Wa + 30;
            c2step<true >(aL, aH, carry, Db + 0 * 8, Wb + 0);
            c2step<false>(aL, aH, carry, Db + 1 * 8, Wb + 6);
            c2step<true >(aL, aH, carry, Db + 2 * 8, Wb + 12);
            c2step<false>(aL, aH, carry, Db + 3 * 8, Wb + 18);
            c2step<true >(aL, aH, carry, Db + 4 * 8, Wb + 24);
        }
        float* O = dout + OFF_C2OUT + ((bi * 20 + co) * 8 + row) * 8;
        float4 v;
        v.x = i2f8((int)aL[0]); v.y = i2f8((int)aL[1]);
        v.z = i2f8((int)aL[2]); v.w = i2f8((int)aL[3]);
        *(float4*)(O + 0) = v;
        v.x = i2f8((int)aH[0]); v.y = i2f8((int)aH[1]);
        v.z = i2f8((int)aH[2]); v.w = i2f8((int)aH[3]);
        *(float4*)(O + 4) = v;
    } else {
        int acc[8];
        int bq = g_b2[co];
#pragma unroll
        for (int j = 0; j < 8; j++) acc[j] = bq;
        const float* X = sx + img * 1440;
#pragma unroll 1
        for (int ci = 0; ci < 10; ci++) {
#pragma unroll
            for (int p = 0; p < 5; p++) {
                float xr[12];
                const float4* xp = (const float4*)(X + ci * 144 + (row + p) * 12);
#pragma unroll
                for (int i = 0; i < 3; i++) {
                    float4 v = xp[i];
                    xr[4 * i + 0] = v.x; xr[4 * i + 1] = v.y;
                    xr[4 * i + 2] = v.z; xr[4 * i + 3] = v.w;
                }
                const ull* wp = W + (ci * 5 + p) * 6;
#pragma unroll
                for (int q = 0; q < 5; q++) {
                    float w = __uint_as_float(lo32(wp[q]));
#pragma unroll
                    for (int j = 0; j < 8; j++) {
                        float y = fmaf(xr[j + q], w, MAGICF);
                        y = fminf(fmaxf(y, CLAMP_LO), CLAMP_HI);
                        acc[j] += __float_as_int(y) - MAGICIi;
                    }
                }
            }
        }
        float* O = dout + OFF_C2OUT + ((bi * 20 + co) * 8 + row) * 8;
#pragma unroll
        for (int j = 0; j < 8; j += 4) {
            float4 v;
            v.x = i2f8(acc[j + 0]); v.y = i2f8(acc[j + 1]);
            v.z = i2f8(acc[j + 2]); v.w = i2f8(acc[j + 3]);
            *(float4*)(O + j) = v;
        }
    }
}

// ---------------------------------------------------------------------------
// fc: block = 256 threads, 4 batch rows, grid 512. Transposed L1-resident
// weights; vectorized pool phase; 4 accumulator chains in FC1.
__global__ void __launch_bounds__(256) fc_kernel(float* __restrict__ dout) {
    __shared__ short xqs[4 * 320];
    __shared__ short x2s[4 * 64];
    __shared__ float v2s[4 * 16];

    int t = threadIdx.x;
    int blk = blockIdx.x;               // rows blk*4 .. blk*4+3

    // phase 1: pool2 + relu + quant; thread = 4 pooled outputs of one
    // channel-row: i = (r, c, rr), 4*20*4 = 320 items.
#pragma unroll
    for (int ii = 0; ii < 2; ii++) {
        int i = ii * 256 + t;
        if (i < 320) {
            int r = i / 80;
            int rem = i % 80;
            int c = rem / 4;
            int rr = rem % 4;
            int rowI = blk * 4 + r;
            const float4* base =
                (const float4*)(dout + OFF_C2OUT + rowI * 1280 + c * 64 + rr * 16);
            float4 A0 = base[0];   // in-row 2rr, cols 0..3
            float4 A1 = base[1];   // in-row 2rr, cols 4..7
            float4 B0 = base[2];   // in-row 2rr+1, cols 0..3
            float4 B1 = base[3];   // in-row 2rr+1, cols 4..7
            float o0 = fmaxf(fmaxf(A0.x, A0.y), fmaxf(B0.x, B0.y));
            float o1 = fmaxf(fmaxf(A0.z, A0.w), fmaxf(B0.z, B0.w));
            float o2 = fmaxf(fmaxf(A1.x, A1.y), fmaxf(B1.x, B1.y));
            float o3 = fmaxf(fmaxf(A1.z, A1.w), fmaxf(B1.z, B1.w));
            o0 = fmaxf(o0, 0.0f); o1 = fmaxf(o1, 0.0f);
            o2 = fmaxf(o2, 0.0f); o3 = fmaxf(o3, 0.0f);
            int k = c * 16 + rr * 4;
            float4 ov; ov.x = o0; ov.y = o1; ov.z = o2; ov.w = o3;
            *(float4*)(dout + OFF_FC1IN + rowI * 320 + k) = ov;
            short4 qv;
            qv.x = (short)iclamp(__float2int_rn(o0 * 256.0f), QLO, QHI);
            qv.y = (short)iclamp(__float2int_rn(o1 * 256.0f), QLO, QHI);
            qv.z = (short)iclamp(__float2int_rn(o2 * 256.0f), QLO, QHI);
            qv.w = (short)iclamp(__float2int_rn(o3 * 256.0f), QLO, QHI);
            *(short4*)(&xqs[r * 320 + k]) = qv;
        }
    }
    __syncthreads();

    // phase 2: FC1. thread = (o = t%50, r = t/50), 200 active, 4 chains.
    if (t < 200) {
        int o = t % 50;
        int r = t / 50;
        const short* xx = &xqs[r * 320];
        const short* wp = &g_w1t[o];
        int S0 = 0, S1 = 0, S2 = 0, S3 = 0;
#pragma unroll 8
        for (int k = 0; k < 80; k++) {
            S0 += (int)xx[k]       * (int)__ldg(&wp[k * 64]);
            S1 += (int)xx[k + 80]  * (int)__ldg(&wp[(k + 80) * 64]);
            S2 += (int)xx[k + 160] * (int)__ldg(&wp[(k + 160) * 64]);
            S3 += (int)xx[k + 240] * (int)__ldg(&wp[(k + 240) * 64]);
        }
        int S = (g_f1b[o] << 8) + ((S0 + S1) + (S2 + S3));
        S = iclamp(S, -524288, 458752);   // [-8, 7] * 65536
        int q = rhe8(S);
        int rowI = blk * 4 + r;
        float f = q * 0.00390625f;
        dout[OFF_FC1OUT + rowI * 50 + o] = f;
        int qr = q > 0 ? q : 0;
        dout[OFF_FC2IN + rowI * 50 + o] = qr * 0.00390625f;
        x2s[r * 64 + o] = (short)qr;
    }
    __syncthreads();

    // phase 3: FC2 (40 dots of length 50)
    if (t < 40) {
        int r = t / 10;
        int o = t % 10;
        int S = g_f2b[o] << 8;
        const short* xx = &x2s[r * 64];
        const short* wp = &g_w2t[o];
#pragma unroll
        for (int k = 0; k < 50; k++) S += (int)xx[k] * (int)__ldg(&wp[k * 16]);
        S = iclamp(S, -524288, 458752);
        int q = rhe8(S);
        float f = q * 0.00390625f;
        int rowI = blk * 4 + r;
        dout[OFF_FC2OUT + rowI * 10 + o] = f;
        v2s[r * 16 + o] = f;
    }
    __syncthreads();

    // phase 4: log_softmax
    if (t < 40) {
        int r = t / 10;
        int o = t % 10;
        const float* v = &v2s[r * 16];
        float m = v[0];
#pragma unroll
        for (int k = 1; k < 10; k++) m = fmaxf(m, v[k]);
        float s = 0.0f;
#pragma unroll
        for (int k = 0; k < 10; k++) s += expf(v[k] - m);
        int rowI = blk * 4 + r;
        dout[OFF_LOGP + rowI * 10 + o] = v[o] - m - logf(s);
    }
}

// ---------------------------------------------------------------------------
extern "C" void kernel_launch(void* const* d_in, const int* in_sizes, int n_in,
                              void* d_out, int out_size) {
    const float* x   = (const float*)d_in[0];
    const float* w1  = (const float*)d_in[1];
    const float* b1  = (const float*)d_in[2];
    const float* w2  = (const float*)d_in[3];
    const float* b2  = (const float*)d_in[4];
    const float* f1w = (const float*)d_in[5];
    const float* f1b = (const float*)d_in[6];
    const float* f2w = (const float*)d_in[7];
    const float* f2b = (const float*)d_in[8];
    float* out = (float*)d_out;

    prep_kernel<<<64, 256>>>(w1, b1, w2, b2, f1w, f1b, f2w, f2b);
    conv1_kernel<<<2048, 256>>>((const float4*)x, out);
    conv2_kernel<<<2048, 160>>>(out);
    fc_kernel<<<512, 256>>>(out);
}

// round 10
// speedup vs baseline: 1.7195x; 1.7195x over previous
#include <cuda_runtime.h>

// ---------------------------------------------------------------------------
// Quantized LeNet, exact fixed-point semantics.
// APREC=8, PPREC=8, IWIDTH=3 -> clamp to [-8.0, +7.0], grid 1/256.
//
// round_half_even(x*w256) == fmaf(x, w256, MAGIC) - MAGIC (MAGIC=1.5*2^23).
// Conv fast path (per-block proof the clamp is a no-op): fma.rn.f32x2 rounds
// TWO pixels per fma; IADD3 merges two 32-bit halves per alu op; magic bias
// removed once via acc init = bias - ntaps*MAGICI (mod 2^32).
// Clamped scalar fallback per block keeps ANY input exact.
// R10: revert to R8 structure (R9's smem D-packs crushed residency);
// conv2+pool2+FC1+FC2+log_softmax merged into ONE kernel (dynamic smem) to
// kill the fc launch and the 10MB conv2_output round-trip.
// ---------------------------------------------------------------------------

typedef unsigned long long ull;

#define MAGICF 12582912.0f
#define MAGICI 0x4B400000u
#define MAGICIi 0x4B400000
#define MAGIC2 0x4B4000004B400000ULL
#define CLAMP_LO (MAGICF - 2048.0f)
#define CLAMP_HI (MAGICF + 1792.0f)   // QMAX = +7.0
#define QLO (-2048)
#define QHI 1792
#define SAFE_BOUND 458624             // 1792*256 - 128

#define OFF_LOGP   0
#define OFF_C1IN   20480
#define OFF_C1OUT  1626112
#define OFF_C2IN   13422592
#define OFF_C2OUT  16371712
#define OFF_FC1IN  18993152
#define OFF_FC1OUT 19648512
#define OFF_FC2IN  19750912
#define OFF_FC2OUT 19853312

__device__ ull   g_w1b[256];         // conv1 w*256 broadcast pairs (w,w)
__device__ int   g_b1[16];
__device__ ull   g_w2b[6016];        // conv2 broadcast pairs, [20][10][5][6]
__device__ int   g_b2[32];
__device__ short g_w1t[320 * 64];    // fc1 w transposed [k][o], o padded to 64
__device__ int   g_f1b[64];
__device__ short g_w2t[50 * 16];     // fc2 w transposed [k][o], o padded to 16
__device__ int   g_f2b[16];
__device__ int   g_maxw1 = 0;        // idempotent atomicMax targets
__device__ int   g_maxw2 = 0;

__device__ __forceinline__ int iclamp(int v, int lo, int hi) {
    return v < lo ? lo : (v > hi ? hi : v);
}
__device__ __forceinline__ int rhe8(int S) {
    return (S + 127 + ((S >> 8) & 1)) >> 8;
}
__device__ __forceinline__ unsigned lo32(ull v) { return (unsigned)v; }
__device__ __forceinline__ unsigned hi32(ull v) { return (unsigned)(v >> 32); }
__device__ __forceinline__ ull mkpack(unsigned lo, unsigned hi) {
    ull d;
    asm("mov.b64 %0, {%1, %2};" : "=l"(d) : "r"(lo), "r"(hi));
    return d;
}
__device__ __forceinline__ ull ffma2m(ull x, ull w) {
    ull d;
    ull m = MAGIC2;
    asm("fma.rn.f32x2 %0, %1, %2, %3;" : "=l"(d) : "l"(x), "l"(w), "l"(m));
    return d;
}
__device__ __forceinline__ float i2f8(int v) {
    return __int2float_rn(v) * 0.00390625f;
}

template <int NW>
__device__ __forceinline__ void blockAtomicMax(int v, int* dst) {
    __shared__ int sm[NW];
    v = __reduce_max_sync(0xffffffffu, v);
    int w = threadIdx.x >> 5;
    if ((threadIdx.x & 31) == 0) sm[w] = v;
    __syncthreads();
    if (threadIdx.x == 0) {
        int m = sm[0];
#pragma unroll
        for (int i = 1; i < NW; i++) m = max(m, sm[i]);
        atomicMax(dst, m);
    }
}

// ---------------------------------------------------------------------------
// prep: 64 blocks x 256 threads, grid-stride over every table.
__global__ void __launch_bounds__(256) prep_kernel(
        const float* __restrict__ w1, const float* __restrict__ b1,
        const float* __restrict__ w2, const float* __restrict__ b2,
        const float* __restrict__ f1w, const float* __restrict__ f1b,
        const float* __restrict__ f2w, const float* __restrict__ f2b) {
    int gt = blockIdx.x * 256 + threadIdx.x;
    const int gs = 64 * 256;
    int m1 = 0, m2 = 0;

    for (int i = gt; i < 250; i += gs) {
        float q = rintf(w1[i] * 256.0f);
        unsigned u = __float_as_uint(q);
        g_w1b[i] = ((ull)u << 32) | u;
        m1 = max(m1, abs((int)q));
    }
    for (int i = gt; i < 10; i += gs) g_b1[i] = __float2int_rn(b1[i] * 256.0f);
    for (int i = gt; i < 6000; i += gs) {
        int q = i % 6;
        int rest = i / 6;
        int p = rest % 5;
        int cc = rest / 5;            // cout*10 + cin
        int cin = cc % 10;
        int cout = cc / 10;
        float v = 0.0f;
        if (q < 5) {
            v = rintf(w2[((cout * 10 + cin) * 5 + p) * 5 + q] * 256.0f);
            m2 = max(m2, abs((int)v));
        }
        unsigned u = __float_as_uint(v);
        g_w2b[i] = ((ull)u << 32) | u;
    }
    for (int i = gt; i < 20; i += gs) g_b2[i] = __float2int_rn(b2[i] * 256.0f);

    for (int i = gt; i < 320 * 64; i += gs) {
        int k = i >> 6;
        int o = i & 63;
        short v = 0;
        if (o < 50) v = (short)iclamp(__float2int_rn(f1w[o * 320 + k] * 256.0f),
                                      QLO, QHI);
        g_w1t[i] = v;
    }
    for (int i = gt; i < 50; i += gs)
        g_f1b[i] = iclamp(__float2int_rn(f1b[i] * 256.0f), QLO, QHI);
    for (int i = gt; i < 50 * 16; i += gs) {
        int k = i >> 4;
        int o = i & 15;
        short v = 0;
        if (o < 10) v = (short)iclamp(__float2int_rn(f2w[o * 50 + k] * 256.0f),
                                      QLO, QHI);
        g_w2t[i] = v;
    }
    for (int i = gt; i < 10; i += gs)
        g_f2b[i] = iclamp(__float2int_rn(f2b[i] * 256.0f), QLO, QHI);

    blockAtomicMax<8>(m1, &g_maxw1);
    __syncthreads();
    blockAtomicMax<8>(m2, &g_maxw2);
}

// ---------------------------------------------------------------------------
// conv1 (+ input quant + pool1), one image per 256-thread block. (R8 version)

__device__ __forceinline__ void c1taps6(unsigned* acc, const ull* E, const ull* O,
                                        const ull* w) {
    ull w0 = w[0];
    ull w1 = w[1];
    ull w2 = w[2];
    ull w3 = w[3];
    ull w4 = w[4];
#pragma unroll
    for (int k = 0; k < 6; k++) {
        ull y0 = ffma2m(E[k], w0);
        ull y1 = ffma2m(O[k], w1);
        ull y2 = ffma2m(E[k + 1], w2);
        ull y3 = ffma2m(O[k + 1], w3);
        ull y4 = ffma2m(E[k + 2], w4);
        acc[2 * k] = acc[2 * k] + lo32(y0) + lo32(y1);
        acc[2 * k] = acc[2 * k] + lo32(y2) + lo32(y3);
        acc[2 * k] = acc[2 * k] + lo32(y4);
        acc[2 * k + 1] = acc[2 * k + 1] + hi32(y0) + hi32(y1);
        acc[2 * k + 1] = acc[2 * k + 1] + hi32(y2) + hi32(y3);
        acc[2 * k + 1] = acc[2 * k + 1] + hi32(y4);
    }
}

__device__ __forceinline__ void conv1_epilogue(float* dout, int b, int co, int R,
                                               int h, const int* acc0,
                                               const int* acc1) {
    float* Ox = dout + OFF_C1OUT + ((b * 10 + co) * 24 + 2 * R) * 24 + 12 * h;
#pragma unroll
    for (int j = 0; j < 12; j += 4) {
        float4 v0, v1;
        v0.x = i2f8(acc0[j + 0]); v0.y = i2f8(acc0[j + 1]);
        v0.z = i2f8(acc0[j + 2]); v0.w = i2f8(acc0[j + 3]);
        v1.x = i2f8(acc1[j + 0]); v1.y = i2f8(acc1[j + 1]);
        v1.z = i2f8(acc1[j + 2]); v1.w = i2f8(acc1[j + 3]);
        *(float4*)(Ox + j) = v0;
        *(float4*)(Ox + 24 + j) = v1;
    }
    float* P = dout + OFF_C2IN + ((b * 10 + co) * 12 + R) * 12 + 6 * h;
#pragma unroll
    for (int j = 0; j < 6; j += 2) {
        int m0 = max(max(acc0[2 * j], acc0[2 * j + 1]),
                     max(acc1[2 * j], acc1[2 * j + 1]));
        int m1 = max(max(acc0[2 * j + 2], acc0[2 * j + 3]),
                     max(acc1[2 * j + 2], acc1[2 * j + 3]));
        m0 = max(m0, 0);
        m1 = max(m1, 0);
        float2 v;
        v.x = m0 * 0.00390625f;
        v.y = m1 * 0.00390625f;
        *(float2*)(P + j) = v;
    }
}

__global__ void __launch_bounds__(256) conv1_kernel(const float4* __restrict__ xin,
                                                    float* __restrict__ dout) {
    __shared__ __align__(16) float sx[784];
    __shared__ __align__(16) ull sw[250];
    __shared__ int red[8];

    int b = blockIdx.x;
    int t = threadIdx.x;

    int mx = 0;
    if (t < 196) {
        float4 v = xin[b * 196 + t];
        int q0 = __float2int_rn(v.x * 256.0f);
        int q1 = __float2int_rn(v.y * 256.0f);
        int q2 = __float2int_rn(v.z * 256.0f);
        int q3 = __float2int_rn(v.w * 256.0f);
        v.x = q0 * 0.00390625f; v.y = q1 * 0.00390625f;
        v.z = q2 * 0.00390625f; v.w = q3 * 0.00390625f;
        ((float4*)sx)[t] = v;
        ((float4*)(dout + OFF_C1IN + b * 784))[t] = v;
        mx = max(max(abs(q0), abs(q1)), max(abs(q2), abs(q3)));
    }
    if (t < 250) sw[t] = g_w1b[t];

    mx = __reduce_max_sync(0xffffffffu, mx);
    if ((t & 31) == 0) red[t >> 5] = mx;
    __syncthreads();
    int xmax = red[0];
#pragma unroll
    for (int i = 1; i < 8; i++) xmax = max(xmax, red[i]);
    bool safe = (long long)xmax * (long long)g_maxw1 <= SAFE_BOUND;

    if (t >= 240) return;
    int co = t / 24;
    int rem = t % 24;
    int R = rem >> 1;
    int h = t & 1;
    const float* X = sx + R * 56 + 12 * h;

    if (safe) {
        unsigned bias = (unsigned)g_b1[co] - 25u * MAGICI;
        unsigned acc0[12], acc1[12];
#pragma unroll
        for (int j = 0; j < 12; j++) { acc0[j] = bias; acc1[j] = bias; }
#pragma unroll
        for (int rr = 0; rr < 6; rr++) {
            ull E[8];
            const ulonglong2* xp = (const ulonglong2*)(X + rr * 28);
#pragma unroll
            for (int i = 0; i < 4; i++) {
                ulonglong2 v = xp[i];
                E[2 * i] = v.x;
                E[2 * i + 1] = v.y;
            }
            ull O[7];
#pragma unroll
            for (int i = 0; i < 7; i++) O[i] = mkpack(hi32(E[i]), lo32(E[i + 1]));
            if (rr < 5)  c1taps6(acc0, E, O, sw + co * 25 + rr * 5);
            if (rr >= 1) c1taps6(acc1, E, O, sw + co * 25 + (rr - 1) * 5);
        }
        conv1_epilogue(dout, b, co, R, h, (const int*)acc0, (const int*)acc1);
    } else {
        int bq = g_b1[co];
        int acc0[12], acc1[12];
#pragma unroll
        for (int j = 0; j < 12; j++) { acc0[j] = bq; acc1[j] = bq; }
#pragma unroll
        for (int rr = 0; rr < 6; rr++) {
            float xr[16];
#pragma unroll
            for (int i = 0; i < 4; i++) {
                float4 v = ((const float4*)(X + rr * 28))[i];
                xr[4 * i + 0] = v.x; xr[4 * i + 1] = v.y;
                xr[4 * i + 2] = v.z; xr[4 * i + 3] = v.w;
            }
#pragma unroll
            for (int pass = 0; pass < 2; pass++) {
                int p = pass == 0 ? rr : rr - 1;
                if (p < 0 || p > 4) continue;
                int* acc = pass == 0 ? acc0 : acc1;
#pragma unroll
                for (int q = 0; q < 5; q++) {
                    float w = __uint_as_float(lo32(sw[co * 25 + p * 5 + q]));
#pragma unroll
                    for (int j = 0; j < 12; j++) {
                        float y = fmaf(xr[j + q], w, MAGICF);
                        y = fminf(fmaxf(y, CLAMP_LO), CLAMP_HI);
                        acc[j] += __float_as_int(y) - MAGICIi;
                    }
                }
            }
        }
        conv1_epilogue(dout, b, co, R, h, acc0, acc1);
    }
}

// ---------------------------------------------------------------------------
// conv2 + pool2 + FC1 + FC2 + log_softmax, fused.
// Block = 320 threads = (2 images x 20 couts x 8 rows), grid 1024.
// Dynamic smem layout (bytes):
#define SM_W    0        // 6000 ull  = 48000
#define SM_X    48000    // 2880 f32  = 11520
#define SM_ACC  59520    // 2560 int  = 10240
#define SM_XQ   69760    // 640 short = 1280
#define SM_X2   71040    // 128 short = 256
#define SM_V2   71296    // 32 f32    = 128
#define SM_RED  71424    // 10 int    = 40
#define SM_TOTAL 71488

template <bool CONSUME>
__device__ __forceinline__ void c2step(unsigned acc[8], ull carry[4],
                                       const float* Xrow, const ull* wp) {
    ull E[6];
    const ulonglong2* xp = (const ulonglong2*)Xrow;
#pragma unroll
    for (int i = 0; i < 3; i++) {
        ulonglong2 v = xp[i];
        E[2 * i] = v.x;
        E[2 * i + 1] = v.y;
    }
    ull O[5];
#pragma unroll
    for (int i = 0; i < 5; i++) O[i] = mkpack(hi32(E[i]), lo32(E[i + 1]));
    const ulonglong2* wv = (const ulonglong2*)wp;
    ulonglong2 wa = wv[0];
    ulonglong2 wb = wv[1];
    ulonglong2 wc = wv[2];
#pragma unroll
    for (int k = 0; k < 4; k++) {
        ull y0 = ffma2m(E[k], wa.x);
        ull y1 = ffma2m(O[k], wa.y);
        ull y2 = ffma2m(E[k + 1], wb.x);
        ull y3 = ffma2m(O[k + 1], wb.y);
        ull y4 = ffma2m(E[k + 2], wc.x);
        acc[2 * k] = acc[2 * k] + lo32(y0) + lo32(y1);
        acc[2 * k] = acc[2 * k] + lo32(y2) + lo32(y3);
        acc[2 * k + 1] = acc[2 * k + 1] + hi32(y0) + hi32(y1);
        acc[2 * k + 1] = acc[2 * k + 1] + hi32(y2) + hi32(y3);
        if (CONSUME) {
            acc[2 * k]     = acc[2 * k]     + lo32(y4) + lo32(carry[k]);
            acc[2 * k + 1] = acc[2 * k + 1] + hi32(y4) + hi32(carry[k]);
        } else {
            carry[k] = y4;
        }
    }
}

__global__ void __launch_bounds__(320) conv2fc_kernel(float* __restrict__ dout) {
    extern __shared__ __align__(16) char smem[];
    ull*   sw   = (ull*)(smem + SM_W);
    float* sx   = (float*)(smem + SM_X);
    int*   sacc = (int*)(smem + SM_ACC);
    short* xqs  = (short*)(smem + SM_XQ);
    short* x2s  = (short*)(smem + SM_X2);
    float* v2s  = (float*)(smem + SM_V2);
    int*   red  = (int*)(smem + SM_RED);

    int ip = blockIdx.x;      // image pair 0..1023
    int t = threadIdx.x;

    // stage all conv2 weights (48KB) + x (2 images)
    const ulonglong2* wsrc = (const ulonglong2*)g_w2b;
    for (int i = t; i < 3000; i += 320) ((ulonglong2*)sw)[i] = wsrc[i];

    const float4* xs = (const float4*)(dout + OFF_C2IN + ip * 2880);
    int mx = 0;
    for (int i = t; i < 720; i += 320) {
        float4 v = xs[i];
        ((float4*)sx)[i] = v;
        int q0 = __float2int_rn(v.x * 256.0f);
        int q1 = __float2int_rn(v.y * 256.0f);
        int q2 = __float2int_rn(v.z * 256.0f);
        int q3 = __float2int_rn(v.w * 256.0f);
        mx = max(mx, max(max(abs(q0), abs(q1)), max(abs(q2), abs(q3))));
    }
    mx = __reduce_max_sync(0xffffffffu, mx);
    if ((t & 31) == 0) red[t >> 5] = mx;
    __syncthreads();
    int xmax = red[0];
#pragma unroll
    for (int i = 1; i < 10; i++) xmax = max(xmax, red[i]);
    bool safe = (long long)xmax * (long long)g_maxw2 <= SAFE_BOUND;

    int img = t / 160;
    int r = t % 160;
    int co = r / 8;           // 0..19
    int row = r % 8;
    const float* X = sx + img * 1440;
    const ull* W = sw + co * 300;
    int bi = ip * 2 + img;

    int accs[8];              // final counts for this (img,co,row)
    if (safe) {
        unsigned acc[8];
        unsigned bias = (unsigned)g_b2[co] - 250u * MAGICI;
#pragma unroll
        for (int j = 0; j < 8; j++) acc[j] = bias;
        ull carry[4];
#pragma unroll 1
        for (int ci2 = 0; ci2 < 5; ci2++) {
            int cA = 2 * ci2;
            const float* Xa = X + cA * 144 + row * 12;
            const ull* Wa = W + cA * 30;
            c2step<false>(acc, carry, Xa + 0 * 12, Wa + 0);
            c2step<true >(acc, carry, Xa + 1 * 12, Wa + 6);
            c2step<false>(acc, carry, Xa + 2 * 12, Wa + 12);
            c2step<true >(acc, carry, Xa + 3 * 12, Wa + 18);
            c2step<false>(acc, carry, Xa + 4 * 12, Wa + 24);
            const float* Xb = Xa + 144;
            const ull* Wb = Wa + 30;
            c2step<true >(acc, carry, Xb + 0 * 12, Wb + 0);
            c2step<false>(acc, carry, Xb + 1 * 12, Wb + 6);
            c2step<true >(acc, carry, Xb + 2 * 12, Wb + 12);
            c2step<false>(acc, carry, Xb + 3 * 12, Wb + 18);
            c2step<true >(acc, carry, Xb + 4 * 12, Wb + 24);
        }
#pragma unroll
        for (int j = 0; j < 8; j++) accs[j] = (int)acc[j];
    } else {
        int acc[8];
        int bq = g_b2[co];
#pragma unroll
        for (int j = 0; j < 8; j++) acc[j] = bq;
#pragma unroll 1
        for (int ci = 0; ci < 10; ci++) {
#pragma unroll
            for (int p = 0; p < 5; p++) {
                float xr[12];
                const float4* xp = (const float4*)(X + ci * 144 + (row + p) * 12);
#pragma unroll
                for (int i = 0; i < 3; i++) {
                    float4 v = xp[i];
                    xr[4 * i + 0] = v.x; xr[4 * i + 1] = v.y;
                    xr[4 * i + 2] = v.z; xr[4 * i + 3] = v.w;
                }
                const ull* wp = W + (ci * 5 + p) * 6;
#pragma unroll
                for (int q = 0; q < 5; q++) {
                    float w = __uint_as_float(lo32(wp[q]));
#pragma unroll
                    for (int j = 0; j < 8; j++) {
                        float y = fmaf(xr[j + q], w, MAGICF);
                        y = fminf(fmaxf(y, CLAMP_LO), CLAMP_HI);
                        acc[j] += __float_as_int(y) - MAGICIi;
                    }
                }
            }
        }
#pragma unroll
        for (int j = 0; j < 8; j++) accs[j] = acc[j];
    }

    // write conv2_output + stash counts for pooling
    {
        float* O = dout + OFF_C2OUT + ((bi * 20 + co) * 8 + row) * 8;
        float4 v;
        v.x = i2f8(accs[0]); v.y = i2f8(accs[1]);
        v.z = i2f8(accs[2]); v.w = i2f8(accs[3]);
        *(float4*)(O + 0) = v;
        v.x = i2f8(accs[4]); v.y = i2f8(accs[5]);
        v.z = i2f8(accs[6]); v.w = i2f8(accs[7]);
        *(float4*)(O + 4) = v;
        int* A = sacc + ((img * 20 + co) * 8 + row) * 8;
#pragma unroll
        for (int j = 0; j < 8; j++) A[j] = accs[j];
    }
    __syncthreads();

    // pool2 + relu + quant: 640 outputs; thread t handles k=t for both images
    if (t < 320) {
        int c = t >> 4;
        int rem = t & 15;
        int pr = rem >> 2;
        int pc = rem & 3;
#pragma unroll
        for (int im = 0; im < 2; im++) {
            const int* A = sacc + ((im * 20 + c) * 8 + 2 * pr) * 8 + 2 * pc;
            int m = max(max(A[0], A[1]), max(A[8], A[9]));
            m = max(m, 0);
            int rowI = ip * 2 + im;
            dout[OFF_FC1IN + rowI * 320 + t] = m * 0.00390625f;
            xqs[im * 320 + t] = (short)min(m, QHI);
        }
    }
    __syncthreads();

    // FC1: 100 threads = (o 0..49, r 0..1)
    if (t < 100) {
        int o = t % 50;
        int rr = t / 50;
        const short* xx = &xqs[rr * 320];
        const short* wp = &g_w1t[o];
        int S = g_f1b[o] << 8;
#pragma unroll 8
        for (int k = 0; k < 320; k++) S += (int)xx[k] * (int)wp[k * 64];
        S = iclamp(S, -524288, 458752);   // [-8, 7] * 65536
        int q = rhe8(S);
        int rowI = ip * 2 + rr;
        float f = q * 0.00390625f;
        dout[OFF_FC1OUT + rowI * 50 + o] = f;
        int qr = q > 0 ? q : 0;
        dout[OFF_FC2IN + rowI * 50 + o] = qr * 0.00390625f;
        x2s[rr * 64 + o] = (short)qr;
    }
    __syncthreads();

    // FC2: 20 threads = (r 0..1, o 0..9)
    if (t < 20) {
        int rr = t / 10;
        int o = t % 10;
        int S = g_f2b[o] << 8;
        const short* xx = &x2s[rr * 64];
        const short* wp = &g_w2t[o];
#pragma unroll
        for (int k = 0; k < 50; k++) S += (int)xx[k] * (int)wp[k * 16];
        S = iclamp(S, -524288, 458752);
        int q = rhe8(S);
        float f = q * 0.00390625f;
        int rowI = ip * 2 + rr;
        dout[OFF_FC2OUT + rowI * 10 + o] = f;
        v2s[rr * 16 + o] = f;
    }
    __syncthreads();

    // log_softmax
    if (t < 20) {
        int rr = t / 10;
        int o = t % 10;
        const float* v = &v2s[rr * 16];
        float m = v[0];
#pragma unroll
        for (int k = 1; k < 10; k++) m = fmaxf(m, v[k]);
        float s = 0.0f;
#pragma unroll
        for (int k = 0; k < 10; k++) s += expf(v[k] - m);
        int rowI = ip * 2 + rr;
        dout[OFF_LOGP + rowI * 10 + o] = v[o] - m - logf(s);
    }
}

// ---------------------------------------------------------------------------
extern "C" void kernel_launch(void* const* d_in, const int* in_sizes, int n_in,
                              void* d_out, int out_size) {
    const float* x   = (const float*)d_in[0];
    const float* w1  = (const float*)d_in[1];
    const float* b1  = (const float*)d_in[2];
    const float* w2  = (const float*)d_in[3];
    const float* b2  = (const float*)d_in[4];
    const float* f1w = (const float*)d_in[5];
    const float* f1b = (const float*)d_in[6];
    const float* f2w = (const float*)d_in[7];
    const float* f2b = (const float*)d_in[8];
    float* out = (float*)d_out;

    cudaFuncSetAttribute(conv2fc_kernel,
                         cudaFuncAttributeMaxDynamicSharedMemorySize, SM_TOTAL);

    prep_kernel<<<64, 256>>>(w1, b1, w2, b2, f1w, f1b, f2w, f2b);
    conv1_kernel<<<2048, 256>>>((const float4*)x, out);
    conv2fc_kernel<<<1024, 320, SM_TOTAL>>>(out);
}

// round 11
// speedup vs baseline: 1.8556x; 1.0791x over previous
#include <cuda_runtime.h>

// ---------------------------------------------------------------------------
// Quantized LeNet, exact fixed-point semantics.
// APREC=8, PPREC=8, IWIDTH=3 -> clamp to [-8.0, +7.0], grid 1/256.
//
// round_half_even(x*w256) == fmaf(x, w256, MAGIC) - MAGIC (MAGIC=1.5*2^23).
// Conv fast path (per-block proof the clamp is a no-op): fma.rn.f32x2 rounds
// TWO pixels per fma; IADD3 merges two 32-bit halves per alu op; magic bias
// removed once via acc init = bias - ntaps*MAGICI (mod 2^32).
// Clamped scalar fallback per block keeps ANY input exact.
// R11: R8 structure (best known: 108.8us) with the prep kernel DELETED —
// conv1 quantizes its own weights per block and grid-strided slices of
// conv1's 524K threads build the conv2/fc tables; biases quantized inline.
// 3 kernels total.
// ---------------------------------------------------------------------------

typedef unsigned long long ull;

#define MAGICF 12582912.0f
#define MAGICI 0x4B400000u
#define MAGICIi 0x4B400000
#define MAGIC2 0x4B4000004B400000ULL
#define CLAMP_LO (MAGICF - 2048.0f)
#define CLAMP_HI (MAGICF + 1792.0f)   // QMAX = +7.0
#define QLO (-2048)
#define QHI 1792
#define SAFE_BOUND 458624             // 1792*256 - 128

#define OFF_LOGP   0
#define OFF_C1IN   20480
#define OFF_C1OUT  1626112
#define OFF_C2IN   13422592
#define OFF_C2OUT  16371712
#define OFF_FC1IN  18993152
#define OFF_FC1OUT 19648512
#define OFF_FC2IN  19750912
#define OFF_FC2OUT 19853312

__device__ ull   g_w2b[6016];        // conv2 broadcast pairs, [20][10][5][6]
__device__ short g_w1t[320 * 64];    // fc1 w transposed [k][o], o padded to 64
__device__ short g_w2t[50 * 16];     // fc2 w transposed [k][o], o padded to 16
__device__ int   g_maxw2 = 0;        // idempotent atomicMax target

__device__ __forceinline__ int iclamp(int v, int lo, int hi) {
    return v < lo ? lo : (v > hi ? hi : v);
}
__device__ __forceinline__ int rhe8(int S) {
    return (S + 127 + ((S >> 8) & 1)) >> 8;
}
__device__ __forceinline__ unsigned lo32(ull v) { return (unsigned)v; }
__device__ __forceinline__ unsigned hi32(ull v) { return (unsigned)(v >> 32); }
__device__ __forceinline__ ull mkpack(unsigned lo, unsigned hi) {
    ull d;
    asm("mov.b64 %0, {%1, %2};" : "=l"(d) : "r"(lo), "r"(hi));
    return d;
}
__device__ __forceinline__ ull ffma2m(ull x, ull w) {
    ull d;
    ull m = MAGIC2;
    asm("fma.rn.f32x2 %0, %1, %2, %3;" : "=l"(d) : "l"(x), "l"(w), "l"(m));
    return d;
}
__device__ __forceinline__ float i2f8(int v) {
    return __int2float_rn(v) * 0.00390625f;
}

// ---------------------------------------------------------------------------
// conv1 (+ input quant + pool1 + table-prep slice), one image per 256-thread
// block. Thread = (co, R, h): conv1_out rows 2R,2R+1 cols [12h,12h+12),
// pooled row R cols [6h,6h+6).

__device__ __forceinline__ void c1taps6(unsigned* acc, const ull* E, const ull* O,
                                        const ull* w) {
    ull w0 = w[0];
    ull w1 = w[1];
    ull w2 = w[2];
    ull w3 = w[3];
    ull w4 = w[4];
#pragma unroll
    for (int k = 0; k < 6; k++) {
        ull y0 = ffma2m(E[k], w0);
        ull y1 = ffma2m(O[k], w1);
        ull y2 = ffma2m(E[k + 1], w2);
        ull y3 = ffma2m(O[k + 1], w3);
        ull y4 = ffma2m(E[k + 2], w4);
        acc[2 * k] = acc[2 * k] + lo32(y0) + lo32(y1);
        acc[2 * k] = acc[2 * k] + lo32(y2) + lo32(y3);
        acc[2 * k] = acc[2 * k] + lo32(y4);
        acc[2 * k + 1] = acc[2 * k + 1] + hi32(y0) + hi32(y1);
        acc[2 * k + 1] = acc[2 * k + 1] + hi32(y2) + hi32(y3);
        acc[2 * k + 1] = acc[2 * k + 1] + hi32(y4);
    }
}

__device__ __forceinline__ void conv1_epilogue(float* dout, int b, int co, int R,
                                               int h, const int* acc0,
                                               const int* acc1) {
    float* Ox = dout + OFF_C1OUT + ((b * 10 + co) * 24 + 2 * R) * 24 + 12 * h;
#pragma unroll
    for (int j = 0; j < 12; j += 4) {
        float4 v0, v1;
        v0.x = i2f8(acc0[j + 0]); v0.y = i2f8(acc0[j + 1]);
        v0.z = i2f8(acc0[j + 2]); v0.w = i2f8(acc0[j + 3]);
        v1.x = i2f8(acc1[j + 0]); v1.y = i2f8(acc1[j + 1]);
        v1.z = i2f8(acc1[j + 2]); v1.w = i2f8(acc1[j + 3]);
        *(float4*)(Ox + j) = v0;
        *(float4*)(Ox + 24 + j) = v1;
    }
    float* P = dout + OFF_C2IN + ((b * 10 + co) * 12 + R) * 12 + 6 * h;
#pragma unroll
    for (int j = 0; j < 6; j += 2) {
        int m0 = max(max(acc0[2 * j], acc0[2 * j + 1]),
                     max(acc1[2 * j], acc1[2 * j + 1]));
        int m1 = max(max(acc0[2 * j + 2], acc0[2 * j + 3]),
                     max(acc1[2 * j + 2], acc1[2 * j + 3]));
        m0 = max(m0, 0);
        m1 = max(m1, 0);
        float2 v;
        v.x = m0 * 0.00390625f;
        v.y = m1 * 0.00390625f;
        *(float2*)(P + j) = v;
    }
}

__global__ void __launch_bounds__(256) conv1_kernel(
        const float4* __restrict__ xin, const float* __restrict__ w1,
        const float* __restrict__ b1, const float* __restrict__ w2,
        const float* __restrict__ f1w, const float* __restrict__ f2w,
        float* __restrict__ dout) {
    __shared__ __align__(16) float sx[784];
    __shared__ __align__(16) ull sw[250];
    __shared__ int red[8];
    __shared__ int red2[8];

    int b = blockIdx.x;
    int t = threadIdx.x;
    int gt = b * 256 + t;     // 0..524287: prep-slice index

    // ---- prep slice: build conv2/fc tables across the whole grid ----
    // g_w2b (6016 incl. pad; value guard keeps warps uniform)
    if (gt < 6016) {
        int q = gt % 6;
        int rest = gt / 6;
        int p = rest % 5;
        int cc = rest / 5;            // cout*10 + cin
        int cin = cc % 10;
        int cout = cc / 10;
        float v = 0.0f;
        int m2 = 0;
        if (q < 5 && gt < 6000) {
            v = rintf(w2[((cout * 10 + cin) * 5 + p) * 5 + q] * 256.0f);
            m2 = abs((int)v);
        }
        unsigned u = __float_as_uint(v);
        g_w2b[gt] = ((ull)u << 32) | u;
        m2 = __reduce_max_sync(0xffffffffu, m2);
        if ((t & 31) == 0) atomicMax(&g_maxw2, m2);
    }
    // g_w1t (20480 = 640 warps, uniform)
    if (gt < 320 * 64) {
        int k = gt >> 6;
        int o = gt & 63;
        short v = 0;
        if (o < 50) v = (short)iclamp(__float2int_rn(f1w[o * 320 + k] * 256.0f),
                                      QLO, QHI);
        g_w1t[gt] = v;
    }
    // g_w2t (800 = 25 warps, uniform)
    if (gt < 50 * 16) {
        int k = gt >> 4;
        int o = gt & 15;
        short v = 0;
        if (o < 10) v = (short)iclamp(__float2int_rn(f2w[o * 50 + k] * 256.0f),
                                      QLO, QHI);
        g_w2t[gt] = v;
    }

    // ---- stage x (quantize = conv1_input output) and conv1 weights ----
    int mx = 0;
    if (t < 196) {
        float4 v = xin[b * 196 + t];
        int q0 = __float2int_rn(v.x * 256.0f);
        int q1 = __float2int_rn(v.y * 256.0f);
        int q2 = __float2int_rn(v.z * 256.0f);
        int q3 = __float2int_rn(v.w * 256.0f);
        v.x = q0 * 0.00390625f; v.y = q1 * 0.00390625f;
        v.z = q2 * 0.00390625f; v.w = q3 * 0.00390625f;
        ((float4*)sx)[t] = v;
        ((float4*)(dout + OFF_C1IN + b * 784))[t] = v;
        mx = max(max(abs(q0), abs(q1)), max(abs(q2), abs(q3)));
    }
    int mw = 0;
    if (t < 250) {
        float q = rintf(w1[t] * 256.0f);
        unsigned u = __float_as_uint(q);
        sw[t] = ((ull)u << 32) | u;
        mw = abs((int)q);
    }

    mx = __reduce_max_sync(0xffffffffu, mx);
    mw = __reduce_max_sync(0xffffffffu, mw);
    if ((t & 31) == 0) { red[t >> 5] = mx; red2[t >> 5] = mw; }
    __syncthreads();
    int xmax = red[0], wmax = red2[0];
#pragma unroll
    for (int i = 1; i < 8; i++) {
        xmax = max(xmax, red[i]);
        wmax = max(wmax, red2[i]);
    }
    bool safe = (long long)xmax * (long long)wmax <= SAFE_BOUND;

    if (t >= 240) return;
    int co = t / 24;
    int rem = t % 24;
    int R = rem >> 1;
    int h = t & 1;
    const float* X = sx + R * 56 + 12 * h;
    int bq = __float2int_rn(b1[co] * 256.0f);

    if (safe) {
        unsigned bias = (unsigned)bq - 25u * MAGICI;
        unsigned acc0[12], acc1[12];
#pragma unroll
        for (int j = 0; j < 12; j++) { acc0[j] = bias; acc1[j] = bias; }
#pragma unroll
        for (int rr = 0; rr < 6; rr++) {
            ull E[8];
            const ulonglong2* xp = (const ulonglong2*)(X + rr * 28);
#pragma unroll
            for (int i = 0; i < 4; i++) {
                ulonglong2 v = xp[i];
                E[2 * i] = v.x;
                E[2 * i + 1] = v.y;
            }
            ull O[7];
#pragma unroll
            for (int i = 0; i < 7; i++) O[i] = mkpack(hi32(E[i]), lo32(E[i + 1]));
            if (rr < 5)  c1taps6(acc0, E, O, sw + co * 25 + rr * 5);
            if (rr >= 1) c1taps6(acc1, E, O, sw + co * 25 + (rr - 1) * 5);
        }
        conv1_epilogue(dout, b, co, R, h, (const int*)acc0, (const int*)acc1);
    } else {
        int acc0[12], acc1[12];
#pragma unroll
        for (int j = 0; j < 12; j++) { acc0[j] = bq; acc1[j] = bq; }
#pragma unroll
        for (int rr = 0; rr < 6; rr++) {
            float xr[16];
#pragma unroll
            for (int i = 0; i < 4; i++) {
                float4 v = ((const float4*)(X + rr * 28))[i];
                xr[4 * i + 0] = v.x; xr[4 * i + 1] = v.y;
                xr[4 * i + 2] = v.z; xr[4 * i + 3] = v.w;
            }
#pragma unroll
            for (int pass = 0; pass < 2; pass++) {
                int p = pass == 0 ? rr : rr - 1;
                if (p < 0 || p > 4) continue;
                int* acc = pass == 0 ? acc0 : acc1;
#pragma unroll
                for (int q = 0; q < 5; q++) {
                    float w = __uint_as_float(lo32(sw[co * 25 + p * 5 + q]));
#pragma unroll
                    for (int j = 0; j < 12; j++) {
                        float y = fmaf(xr[j + q], w, MAGICF);
                        y = fminf(fmaxf(y, CLAMP_LO), CLAMP_HI);
                        acc[j] += __float_as_int(y) - MAGICIi;
                    }
                }
            }
        }
        conv1_epilogue(dout, b, co, R, h, acc0, acc1);
    }
}

// ---------------------------------------------------------------------------
// conv2: block = 160 threads = (2 images x 10 couts x 8 rows). (R8 body)

template <bool CONSUME>
__device__ __forceinline__ void c2step(unsigned acc[8], ull carry[4],
                                       const float* Xrow, const ull* wp) {
    ull E[6];
    const ulonglong2* xp = (const ulonglong2*)Xrow;
#pragma unroll
    for (int i = 0; i < 3; i++) {
        ulonglong2 v = xp[i];
        E[2 * i] = v.x;
        E[2 * i + 1] = v.y;
    }
    ull O[5];
#pragma unroll
    for (int i = 0; i < 5; i++) O[i] = mkpack(hi32(E[i]), lo32(E[i + 1]));
    const ulonglong2* wv = (const ulonglong2*)wp;
    ulonglong2 wa = wv[0];
    ulonglong2 wb = wv[1];
    ulonglong2 wc = wv[2];
#pragma unroll
    for (int k = 0; k < 4; k++) {
        ull y0 = ffma2m(E[k], wa.x);
        ull y1 = ffma2m(O[k], wa.y);
        ull y2 = ffma2m(E[k + 1], wb.x);
        ull y3 = ffma2m(O[k + 1], wb.y);
        ull y4 = ffma2m(E[k + 2], wc.x);
        acc[2 * k] = acc[2 * k] + lo32(y0) + lo32(y1);
        acc[2 * k] = acc[2 * k] + lo32(y2) + lo32(y3);
        acc[2 * k + 1] = acc[2 * k + 1] + hi32(y0) + hi32(y1);
        acc[2 * k + 1] = acc[2 * k + 1] + hi32(y2) + hi32(y3);
        if (CONSUME) {
            acc[2 * k]     = acc[2 * k]     + lo32(y4) + lo32(carry[k]);
            acc[2 * k + 1] = acc[2 * k + 1] + hi32(y4) + hi32(carry[k]);
        } else {
            carry[k] = y4;
        }
    }
}

__global__ void __launch_bounds__(160) conv2_kernel(const float* __restrict__ b2,
                                                    float* __restrict__ dout) {
    __shared__ __align__(16) float sx[2880];
    __shared__ __align__(16) ull sw[3000];
    __shared__ int red[5];

    int blk = blockIdx.x;     // 0..2047
    int ip = blk >> 1;        // image pair index
    int g = blk & 1;          // cout group (couts 10g..10g+9)
    int t = threadIdx.x;

    const ulonglong2* wsrc = (const ulonglong2*)(g_w2b + g * 3000);
    for (int i = t; i < 1500; i += 160) ((ulonglong2*)sw)[i] = wsrc[i];

    const float4* xs = (const float4*)(dout + OFF_C2IN + ip * 2880);
    int mx = 0;
    for (int i = t; i < 720; i += 160) {
        float4 v = xs[i];
        ((float4*)sx)[i] = v;
        int q0 = __float2int_rn(v.x * 256.0f);
        int q1 = __float2int_rn(v.y * 256.0f);
        int q2 = __float2int_rn(v.z * 256.0f);
        int q3 = __float2int_rn(v.w * 256.0f);
        mx = max(mx, max(max(abs(q0), abs(q1)), max(abs(q2), abs(q3))));
    }
    mx = __reduce_max_sync(0xffffffffu, mx);
    if ((t & 31) == 0) red[t >> 5] = mx;
    __syncthreads();
    int xmax = red[0];
#pragma unroll
    for (int i = 1; i < 5; i++) xmax = max(xmax, red[i]);
    bool safe = (long long)xmax * (long long)g_maxw2 <= SAFE_BOUND;

    int img = t / 80;
    int r = t % 80;
    int co_local = r / 8;
    int row = r % 8;
    int co = g * 10 + co_local;
    const float* X = sx + img * 1440;
    const ull* W = sw + co_local * 300;
    int bi = ip * 2 + img;
    int bq = __float2int_rn(b2[co] * 256.0f);

    if (safe) {
        unsigned acc[8];
        unsigned bias = (unsigned)bq - 250u * MAGICI;
#pragma unroll
        for (int j = 0; j < 8; j++) acc[j] = bias;
        ull carry[4];
#pragma unroll 1
        for (int ci2 = 0; ci2 < 5; ci2++) {
            int cA = 2 * ci2;
            const float* Xa = X + cA * 144 + row * 12;
            const ull* Wa = W + cA * 30;
            c2step<false>(acc, carry, Xa + 0 * 12, Wa + 0);
            c2step<true >(acc, carry, Xa + 1 * 12, Wa + 6);
            c2step<false>(acc, carry, Xa + 2 * 12, Wa + 12);
            c2step<true >(acc, carry, Xa + 3 * 12, Wa + 18);
            c2step<false>(acc, carry, Xa + 4 * 12, Wa + 24);
            const float* Xb = Xa + 144;
            const ull* Wb = Wa + 30;
            c2step<true >(acc, carry, Xb + 0 * 12, Wb + 0);
            c2step<false>(acc, carry, Xb + 1 * 12, Wb + 6);
            c2step<true >(acc, carry, Xb + 2 * 12, Wb + 12);
            c2step<false>(acc, carry, Xb + 3 * 12, Wb + 18);
            c2step<true >(acc, carry, Xb + 4 * 12, Wb + 24);
        }
        float* O = dout + OFF_C2OUT + ((bi * 20 + co) * 8 + row) * 8;
        float4 v;
        v.x = i2f8((int)acc[0]); v.y = i2f8((int)acc[1]);
        v.z = i2f8((int)acc[2]); v.w = i2f8((int)acc[3]);
        *(float4*)(O + 0) = v;
        v.x = i2f8((int)acc[4]); v.y = i2f8((int)acc[5]);
        v.z = i2f8((int)acc[6]); v.w = i2f8((int)acc[7]);
        *(float4*)(O + 4) = v;
    } else {
        int acc[8];
#pragma unroll
        for (int j = 0; j < 8; j++) acc[j] = bq;
#pragma unroll 1
        for (int ci = 0; ci < 10; ci++) {
#pragma unroll
            for (int p = 0; p < 5; p++) {
                float xr[12];
                const float4* xp = (const float4*)(X + ci * 144 + (row + p) * 12);
#pragma unroll
                for (int i = 0; i < 3; i++) {
                    float4 v = xp[i];
                    xr[4 * i + 0] = v.x; xr[4 * i + 1] = v.y;
                    xr[4 * i + 2] = v.z; xr[4 * i + 3] = v.w;
                }
                const ull* wp = W + (ci * 5 + p) * 6;
#pragma unroll
                for (int q = 0; q < 5; q++) {
                    float w = __uint_as_float(lo32(wp[q]));
#pragma unroll
                    for (int j = 0; j < 8; j++) {
                        float y = fmaf(xr[j + q], w, MAGICF);
                        y = fminf(fmaxf(y, CLAMP_LO), CLAMP_HI);
                        acc[j] += __float_as_int(y) - MAGICIi;
                    }
                }
            }
        }
        float* O = dout + OFF_C2OUT + ((bi * 20 + co) * 8 + row) * 8;
#pragma unroll
        for (int j = 0; j < 8; j += 4) {
            float4 v;
            v.x = i2f8(acc[j + 0]); v.y = i2f8(acc[j + 1]);
            v.z = i2f8(acc[j + 2]); v.w = i2f8(acc[j + 3]);
            *(float4*)(O + j) = v;
        }
    }
}

// ---------------------------------------------------------------------------
// fc (R8 body): block = 256 threads, 4 batch rows, grid 512. Transposed
// L1-resident weights; biases quantized inline from raw pointers.
__global__ void __launch_bounds__(256) fc_kernel(const float* __restrict__ f1b,
                                                 const float* __restrict__ f2b,
                                                 float* __restrict__ dout) {
    __shared__ short xqs[4 * 320];
    __shared__ short x2s[4 * 64];
    __shared__ float v2s[4 * 16];

    int t = threadIdx.x;
    int blk = blockIdx.x;               // rows blk*4 .. blk*4+3

    // phase 1: pool2 + relu + quant (writes fc1_input)
#pragma unroll
    for (int ii = 0; ii < 5; ii++) {
        int i = ii * 256 + t;           // 1280 items
        int r = i / 320;
        int k = i % 320;
        int rowI = blk * 4 + r;
        int c = k >> 4;
        int rem = k & 15;
        int rr = rem >> 2;
        int col = rem & 3;
        const float* base = dout + OFF_C2OUT + rowI * 1280 + c * 64 + 2 * rr * 8 + 2 * col;
        float2 a = *(const float2*)base;
        float2 d = *(const float2*)(base + 8);
        float m = fmaxf(fmaxf(a.x, a.y), fmaxf(d.x, d.y));
        m = fmaxf(m, 0.0f);
        dout[OFF_FC1IN + rowI * 320 + k] = m;
        int q = __float2int_rn(m * 256.0f);
        xqs[r * 320 + k] = (short)iclamp(q, QLO, QHI);
    }
    __syncthreads();

    // phase 2: FC1. thread = (o = t%50, r = t/50), 200 active
    if (t < 200) {
        int o = t % 50;
        int r = t / 50;
        int fb = iclamp(__float2int_rn(f1b[o] * 256.0f), QLO, QHI);
        int S = fb << 8;
        const short* xx = &xqs[r * 320];
        const short* wp = &g_w1t[o];
#pragma unroll 8
        for (int k = 0; k < 320; k++) S += (int)xx[k] * (int)wp[k * 64];
        S = iclamp(S, -524288, 458752);   // [-8, 7] * 65536
        int q = rhe8(S);
        int rowI = blk * 4 + r;
        float f = q * 0.00390625f;
        dout[OFF_FC1OUT + rowI * 50 + o] = f;
        int qr = q > 0 ? q : 0;
        dout[OFF_FC2IN + rowI * 50 + o] = qr * 0.00390625f;
        x2s[r * 64 + o] = (short)qr;
    }
    __syncthreads();

    // phase 3: FC2 (40 dots of length 50)
    if (t < 40) {
        int r = t / 10;
        int o = t % 10;
        int fb = iclamp(__float2int_rn(f2b[o] * 256.0f), QLO, QHI);
        int S = fb << 8;
        const short* xx = &x2s[r * 64];
        const short* wp = &g_w2t[o];
#pragma unroll
        for (int k = 0; k < 50; k++) S += (int)xx[k] * (int)wp[k * 16];
        S = iclamp(S, -524288, 458752);
        int q = rhe8(S);
        float f = q * 0.00390625f;
        int rowI = blk * 4 + r;
        dout[OFF_FC2OUT + rowI * 10 + o] = f;
        v2s[r * 16 + o] = f;
    }
    __syncthreads();

    // phase 4: log_softmax
    if (t < 40) {
        int r = t / 10;
        int o = t % 10;
        const float* v = &v2s[r * 16];
        float m = v[0];
#pragma unroll
        for (int k = 1; k < 10; k++) m = fmaxf(m, v[k]);
        float s = 0.0f;
#pragma unroll
        for (int k = 0; k < 10; k++) s += expf(v[k] - m);
        int rowI = blk * 4 + r;
        dout[OFF_LOGP + rowI * 10 + o] = v[o] - m - logf(s);
    }
}

// ---------------------------------------------------------------------------
extern "C" void kernel_launch(void* const* d_in, const int* in_sizes, int n_in,
                              void* d_out, int out_size) {
    const float* x   = (const float*)d_in[0];
    const float* w1  = (const float*)d_in[1];
    const float* b1  = (const float*)d_in[2];
    const float* w2  = (const float*)d_in[3];
    const float* b2  = (const float*)d_in[4];
    const float* f1w = (const float*)d_in[5];
    const float* f1b = (const float*)d_in[6];
    const float* f2w = (const float*)d_in[7];
    const float* f2b = (const float*)d_in[8];
    float* out = (float*)d_out;

    conv1_kernel<<<2048, 256>>>((const float4*)x, w1, b1, w2, f1w, f2w, out);
    conv2_kernel<<<2048, 160>>>(b2, out);
    fc_kernel<<<512, 256>>>(f1b, f2b, out);
}